// round 1
// baseline (speedup 1.0000x reference)
#include <cuda_runtime.h>

#define NN 100000     // nodes
#define NE 1200000    // edges
#define DD 64         // feature dim
#define NG 128        // graphs
#define TPB 128       // nodes per layer-block
#define ZS 68         // smem z row stride (floats), keeps 16B alignment, bank-spread
#define SCAN_B 512
#define NSCAN ((NN + SCAN_B - 1) / SCAN_B)   // 196

// ---- device scratch (module-load allocated; sanctioned workaround) ----
__device__ float g_bufA[NN * DD];
__device__ float g_bufB[NN * DD];
__device__ int   g_rowptr[NN + 1];
__device__ int   g_cursor[NN];
__device__ int   g_counts[NN];
__device__ int   g_srcs[NE];
__device__ int   g_bsum[256];
__device__ int   g_boff[256];
__device__ float g_pool[NG * DD];

// ---------------- CSR build ----------------
__global__ void k_zero() {
    int idx = blockIdx.x * blockDim.x + threadIdx.x;
    int stride = gridDim.x * blockDim.x;
    for (int i = idx; i < NN; i += stride) g_counts[i] = 0;
    for (int i = idx; i < NG * DD; i += stride) g_pool[i] = 0.0f;
}

__global__ void k_hist(const int* __restrict__ ei) {
    int e = blockIdx.x * blockDim.x + threadIdx.x;
    if (e < NE) atomicAdd(&g_counts[ei[NE + e]], 1);
}

__global__ void k_scan1() {
    __shared__ int s[SCAN_B];
    int tid = threadIdx.x;
    int i = blockIdx.x * SCAN_B + tid;
    int c = (i < NN) ? g_counts[i] : 0;
    s[tid] = c;
    __syncthreads();
    #pragma unroll
    for (int off = 1; off < SCAN_B; off <<= 1) {
        int v = 0;
        if (tid >= off) v = s[tid - off];
        __syncthreads();
        s[tid] += v;
        __syncthreads();
    }
    if (i < NN) g_rowptr[i] = s[tid] - c;   // exclusive within block
    if (tid == SCAN_B - 1) g_bsum[blockIdx.x] = s[SCAN_B - 1];
}

__global__ void k_scan2() {
    __shared__ int s[256];
    int tid = threadIdx.x;
    int c = (tid < NSCAN) ? g_bsum[tid] : 0;
    s[tid] = c;
    __syncthreads();
    #pragma unroll
    for (int off = 1; off < 256; off <<= 1) {
        int v = 0;
        if (tid >= off) v = s[tid - off];
        __syncthreads();
        s[tid] += v;
        __syncthreads();
    }
    if (tid < NSCAN) g_boff[tid] = s[tid] - c;  // exclusive
}

__global__ void k_scan3() {
    int i = blockIdx.x * blockDim.x + threadIdx.x;
    if (i < NN) {
        int v = g_rowptr[i] + g_boff[i >> 9];   // 512-element scan blocks
        g_rowptr[i] = v;
        g_cursor[i] = v;
    } else if (i == NN) {
        g_rowptr[NN] = NE;
    }
}

__global__ void k_fill(const int* __restrict__ ei) {
    int e = blockIdx.x * blockDim.x + threadIdx.x;
    if (e < NE) {
        int d = ei[NE + e];
        int pos = atomicAdd(&g_cursor[d], 1);
        g_srcs[pos] = ei[e];
    }
}

// ---------------- fused GIN layer ----------------
// Per block: 128 nodes. Phase 1: agg + self into smem z. Phase 2: z@W1 ->
// BN+ReLU -> y (smem, reusing z) -> y@W2 -> +b2, ReLU -> global.
__global__ __launch_bounds__(256, 2) void k_layer(
    const float* __restrict__ x,
    const float* __restrict__ W1, const float* __restrict__ b1,
    const float* __restrict__ gam, const float* __restrict__ bet,
    const float* __restrict__ W2, const float* __restrict__ b2,
    int l)
{
    extern __shared__ float sm[];
    float* sW1 = sm;            // 4096 floats
    float* sW2 = sm + 4096;     // 4096 floats
    float* sZ  = sm + 8192;     // 128 * 68 floats

    const float* hin = (l == 0) ? x : ((l & 1) ? g_bufA : g_bufB);
    float* hout = (l & 1) ? g_bufB : g_bufA;

    int tid = threadIdx.x;

    // load W1/W2 into smem (coalesced float4)
    {
        const float4* w1g = (const float4*)W1;
        const float4* w2g = (const float4*)W2;
        float4* w1s = (float4*)sW1;
        float4* w2s = (float4*)sW2;
        #pragma unroll
        for (int i = 0; i < 4; i++) {
            w1s[tid + 256 * i] = w1g[tid + 256 * i];
            w2s[tid + 256 * i] = w2g[tid + 256 * i];
        }
    }

    // ---- phase 1: aggregation (16 lanes per node, float4 per lane) ----
    {
        const float4* h4 = (const float4*)hin;
        int grp = tid >> 4, lane = tid & 15;
        int base = blockIdx.x * TPB;
        #pragma unroll
        for (int i = 0; i < 8; i++) {
            int nl = grp * 8 + i;
            int node = base + nl;
            float4 a = make_float4(0.f, 0.f, 0.f, 0.f);
            if (node < NN) {
                a = h4[node * 16 + lane];                 // self (eps = 0)
                int s = g_rowptr[node], e = g_rowptr[node + 1];
                for (int j = s; j < e; j++) {
                    float4 v = h4[g_srcs[j] * 16 + lane];
                    a.x += v.x; a.y += v.y; a.z += v.z; a.w += v.w;
                }
            }
            *(float4*)(&sZ[nl * ZS + 4 * lane]) = a;
        }
    }
    __syncthreads();

    // ---- phase 2: two register-tiled GEMMs ----
    int tx = tid & 15;          // col tile: cols 4tx..4tx+3
    int ty = tid >> 4;          // row tile: rows 8ty..8ty+7
    int base = blockIdx.x * TPB;

    const float RS = rsqrtf(1.0f + 1e-5f);
    float4 gm  = ((const float4*)gam)[tx];
    float4 bt  = ((const float4*)bet)[tx];
    float4 bb1 = ((const float4*)b1)[tx];
    float4 bb2 = ((const float4*)b2)[tx];
    float4 gs, sh;
    gs.x = gm.x * RS; gs.y = gm.y * RS; gs.z = gm.z * RS; gs.w = gm.w * RS;
    sh.x = bt.x + bb1.x * gs.x; sh.y = bt.y + bb1.y * gs.y;
    sh.z = bt.z + bb1.z * gs.z; sh.w = bt.w + bb1.w * gs.w;

    float acc[8][4];
    #pragma unroll
    for (int i = 0; i < 8; i++)
        #pragma unroll
        for (int c = 0; c < 4; c++) acc[i][c] = 0.f;

    const float* zrow = &sZ[ty * 8 * ZS];
    const float4* w1v = (const float4*)sW1;

    #pragma unroll 4
    for (int k = 0; k < 64; k++) {
        float4 w = w1v[k * 16 + tx];
        #pragma unroll
        for (int i = 0; i < 8; i++) {
            float zv = zrow[i * ZS + k];
            acc[i][0] += zv * w.x; acc[i][1] += zv * w.y;
            acc[i][2] += zv * w.z; acc[i][3] += zv * w.w;
        }
    }
    __syncthreads();   // all z reads done before overwriting with y

    #pragma unroll
    for (int i = 0; i < 8; i++) {
        float4 y;
        y.x = fmaxf(acc[i][0] * gs.x + sh.x, 0.f);
        y.y = fmaxf(acc[i][1] * gs.y + sh.y, 0.f);
        y.z = fmaxf(acc[i][2] * gs.z + sh.z, 0.f);
        y.w = fmaxf(acc[i][3] * gs.w + sh.w, 0.f);
        *(float4*)(&sZ[(ty * 8 + i) * ZS + 4 * tx]) = y;
    }
    __syncthreads();

    #pragma unroll
    for (int i = 0; i < 8; i++)
        #pragma unroll
        for (int c = 0; c < 4; c++) acc[i][c] = 0.f;

    const float4* w2v = (const float4*)sW2;
    #pragma unroll 4
    for (int k = 0; k < 64; k++) {
        float4 w = w2v[k * 16 + tx];
        #pragma unroll
        for (int i = 0; i < 8; i++) {
            float zv = zrow[i * ZS + k];
            acc[i][0] += zv * w.x; acc[i][1] += zv * w.y;
            acc[i][2] += zv * w.z; acc[i][3] += zv * w.w;
        }
    }

    float4* out4 = (float4*)hout;
    #pragma unroll
    for (int i = 0; i < 8; i++) {
        int node = base + ty * 8 + i;
        if (node < NN) {
            float4 o;
            o.x = fmaxf(acc[i][0] + bb2.x, 0.f);
            o.y = fmaxf(acc[i][1] + bb2.y, 0.f);
            o.z = fmaxf(acc[i][2] + bb2.z, 0.f);
            o.w = fmaxf(acc[i][3] + bb2.w, 0.f);
            out4[node * 16 + tx] = o;
        }
    }
}

// ---------------- pooling over sorted batch ----------------
__global__ void k_pool(const int* __restrict__ batch) {
    int tid = threadIdx.x;
    int go = tid >> 6;          // 4 groups of 64 lanes
    int d  = tid & 63;
    int start = blockIdx.x * 256 + go * 64;
    if (start >= NN) return;
    int end = min(start + 64, NN);
    const float* h = g_bufA;    // final features live in bufA after layer 4
    int gcur = batch[start];
    float acc = 0.f;
    for (int n = start; n < end; n++) {
        int bg = batch[n];
        float v = h[n * 64 + d];
        if (bg != gcur) {
            atomicAdd(&g_pool[gcur * 64 + d], acc);
            acc = 0.f;
            gcur = bg;
        }
        acc += v;
    }
    atomicAdd(&g_pool[gcur * 64 + d], acc);
}

// ---------------- final linear + relu ----------------
__global__ void k_final(const float* __restrict__ W, const float* __restrict__ b,
                        float* __restrict__ out) {
    int idx = blockIdx.x * blockDim.x + threadIdx.x;  // 8192 outputs
    int g = idx >> 6;
    int c = idx & 63;
    float acc = b[c];
    #pragma unroll 8
    for (int k = 0; k < 64; k++)
        acc += g_pool[g * 64 + k] * W[k * 64 + c];
    out[idx] = fmaxf(acc, 0.f);
}

// ---------------- launch ----------------
extern "C" void kernel_launch(void* const* d_in, const int* in_sizes, int n_in,
                              void* d_out, int out_size) {
    const float* x      = (const float*)d_in[0];
    const int*   ei     = (const int*)d_in[1];
    const int*   batch  = (const int*)d_in[2];
    const float* W1s    = (const float*)d_in[3];
    const float* b1s    = (const float*)d_in[4];
    const float* gammas = (const float*)d_in[5];
    const float* betas  = (const float*)d_in[6];
    const float* W2s    = (const float*)d_in[7];
    const float* b2s    = (const float*)d_in[8];
    const float* lin1_w = (const float*)d_in[9];
    const float* lin1_b = (const float*)d_in[10];
    float* out = (float*)d_out;

    const int SMEM_BYTES = (4096 + 4096 + TPB * ZS) * (int)sizeof(float);  // 67584
    cudaFuncSetAttribute(k_layer, cudaFuncAttributeMaxDynamicSharedMemorySize,
                         SMEM_BYTES);

    // CSR build (deterministic structure; fill order via atomics only permutes
    // fp summation order -> ulp-level noise, well under 1e-3 tolerance)
    k_zero<<<256, 256>>>();
    k_hist<<<(NE + 255) / 256, 256>>>(ei);
    k_scan1<<<NSCAN, SCAN_B>>>();
    k_scan2<<<1, 256>>>();
    k_scan3<<<(NN + 256) / 256, 256>>>();
    k_fill<<<(NE + 255) / 256, 256>>>(ei);

    // 5 fused GIN layers
    int nblocks = (NN + TPB - 1) / TPB;  // 782
    for (int l = 0; l < 5; l++) {
        k_layer<<<nblocks, 256, SMEM_BYTES>>>(
            x, W1s + l * 4096, b1s + l * 64, gammas + l * 64, betas + l * 64,
            W2s + l * 4096, b2s + l * 64, l);
    }

    // global add pool + final linear
    k_pool<<<(NN + 255) / 256, 256>>>(batch);
    k_final<<<32, 256>>>(lin1_w, lin1_b, out);
}

// round 8
// speedup vs baseline: 1.0481x; 1.0481x over previous
#include <cuda_runtime.h>

#define NN 100000     // nodes
#define NE 1200000    // edges
#define DD 64         // feature dim
#define NG 128        // graphs
#define TPB 128       // nodes per layer-block
#define ZT 130        // k-major z row stride (floats): even (8B-aligned pairs), bank-spread
#define SCAN_B 512
#define NSCAN ((NN + SCAN_B - 1) / SCAN_B)   // 196

typedef unsigned long long ull;

// ---- device scratch ----
__device__ float g_bufA[NN * DD];
__device__ float g_bufB[NN * DD];
__device__ int   g_rowptr[NN + 1];
__device__ int   g_cursor[NN];
__device__ int   g_counts[NN];
__device__ int   g_srcs[NE];
__device__ int   g_bsum[256];
__device__ int   g_boff[256];
__device__ float g_pool[NG * DD];

// ---- packed fp32 helpers (sm_100+ f32x2) ----
__device__ __forceinline__ ull pk2(float lo, float hi) {
    ull r;
    asm("mov.b64 %0, {%1, %2};" : "=l"(r) : "f"(lo), "f"(hi));
    return r;
}
__device__ __forceinline__ void ffma2(ull& d, ull a, ull b) {
    // d = a * b + d, elementwise on two packed fp32 lanes (IEEE fp32 exact)
    asm("fma.rn.f32x2 %0, %1, %2, %0;" : "+l"(d) : "l"(a), "l"(b));
}

// ---------------- CSR build ----------------
__global__ void k_zero() {
    int idx = blockIdx.x * blockDim.x + threadIdx.x;
    int stride = gridDim.x * blockDim.x;
    for (int i = idx; i < NN; i += stride) g_counts[i] = 0;
    for (int i = idx; i < NG * DD; i += stride) g_pool[i] = 0.0f;
}

__global__ void k_hist(const int* __restrict__ ei) {
    int e = blockIdx.x * blockDim.x + threadIdx.x;
    if (e < NE) atomicAdd(&g_counts[ei[NE + e]], 1);
}

__global__ void k_scan1() {
    __shared__ int s[SCAN_B];
    int tid = threadIdx.x;
    int i = blockIdx.x * SCAN_B + tid;
    int c = (i < NN) ? g_counts[i] : 0;
    s[tid] = c;
    __syncthreads();
    #pragma unroll
    for (int off = 1; off < SCAN_B; off <<= 1) {
        int v = 0;
        if (tid >= off) v = s[tid - off];
        __syncthreads();
        s[tid] += v;
        __syncthreads();
    }
    if (i < NN) g_rowptr[i] = s[tid] - c;
    if (tid == SCAN_B - 1) g_bsum[blockIdx.x] = s[SCAN_B - 1];
}

__global__ void k_scan2() {
    __shared__ int s[256];
    int tid = threadIdx.x;
    int c = (tid < NSCAN) ? g_bsum[tid] : 0;
    s[tid] = c;
    __syncthreads();
    #pragma unroll
    for (int off = 1; off < 256; off <<= 1) {
        int v = 0;
        if (tid >= off) v = s[tid - off];
        __syncthreads();
        s[tid] += v;
        __syncthreads();
    }
    if (tid < NSCAN) g_boff[tid] = s[tid] - c;
}

__global__ void k_scan3() {
    int i = blockIdx.x * blockDim.x + threadIdx.x;
    if (i < NN) {
        int v = g_rowptr[i] + g_boff[i >> 9];
        g_rowptr[i] = v;
        g_cursor[i] = v;
    } else if (i == NN) {
        g_rowptr[NN] = NE;
    }
}

__global__ void k_fill(const int* __restrict__ ei) {
    int e = blockIdx.x * blockDim.x + threadIdx.x;
    if (e < NE) {
        int d = ei[NE + e];
        int pos = atomicAdd(&g_cursor[d], 1);
        g_srcs[pos] = ei[e];
    }
}

// ---------------- fused GIN layer ----------------
// Block = 128 nodes. Phase 1: agg+self -> zT (k-major smem). Phase 2: two
// register-tiled GEMMs with packed f32x2 FMA (node-pairs packed in b64).
__global__ __launch_bounds__(256, 2) void k_layer(
    const float* __restrict__ x,
    const float* __restrict__ W1, const float* __restrict__ b1,
    const float* __restrict__ gam, const float* __restrict__ bet,
    const float* __restrict__ W2, const float* __restrict__ b2,
    int l)
{
    extern __shared__ float sm[];
    float* sW1 = sm;            // 4096
    float* sW2 = sm + 4096;     // 4096
    float* sZT = sm + 8192;     // 64 * ZT = 8320 floats, layout zT[k][node]

    const float* hin = (l == 0) ? x : ((l & 1) ? g_bufA : g_bufB);
    float* hout = (l & 1) ? g_bufB : g_bufA;

    int tid = threadIdx.x;

    // weights -> smem
    {
        const float4* w1g = (const float4*)W1;
        const float4* w2g = (const float4*)W2;
        float4* w1s = (float4*)sW1;
        float4* w2s = (float4*)sW2;
        #pragma unroll
        for (int i = 0; i < 4; i++) {
            w1s[tid + 256 * i] = w1g[tid + 256 * i];
            w2s[tid + 256 * i] = w2g[tid + 256 * i];
        }
    }

    // ---- phase 1: aggregation, writes z transposed (k-major) ----
    {
        const float4* h4 = (const float4*)hin;
        int grp = tid >> 4, lane = tid & 15;   // lane owns dims 4*lane..4*lane+3
        int base = blockIdx.x * TPB;
        #pragma unroll
        for (int i = 0; i < 8; i++) {
            int nl = grp * 8 + i;
            int node = base + nl;
            float4 a = make_float4(0.f, 0.f, 0.f, 0.f);
            if (node < NN) {
                a = h4[node * 16 + lane];                 // self (eps = 0)
                int s = g_rowptr[node], e = g_rowptr[node + 1];
                for (int j = s; j < e; j += 4) {
                    // prefetch 4 indices to break the idx->data dependency chain
                    int i0 = g_srcs[j];
                    int i1 = (j + 1 < e) ? g_srcs[j + 1] : -1;
                    int i2 = (j + 2 < e) ? g_srcs[j + 2] : -1;
                    int i3 = (j + 3 < e) ? g_srcs[j + 3] : -1;
                    float4 v0 = h4[i0 * 16 + lane];
                    a.x += v0.x; a.y += v0.y; a.z += v0.z; a.w += v0.w;
                    if (i1 >= 0) {
                        float4 v = h4[i1 * 16 + lane];
                        a.x += v.x; a.y += v.y; a.z += v.z; a.w += v.w;
                    }
                    if (i2 >= 0) {
                        float4 v = h4[i2 * 16 + lane];
                        a.x += v.x; a.y += v.y; a.z += v.z; a.w += v.w;
                    }
                    if (i3 >= 0) {
                        float4 v = h4[i3 * 16 + lane];
                        a.x += v.x; a.y += v.y; a.z += v.z; a.w += v.w;
                    }
                }
            }
            int k0 = 4 * lane;
            sZT[(k0 + 0) * ZT + nl] = a.x;
            sZT[(k0 + 1) * ZT + nl] = a.y;
            sZT[(k0 + 2) * ZT + nl] = a.z;
            sZT[(k0 + 3) * ZT + nl] = a.w;
        }
    }
    __syncthreads();

    // ---- phase 2: GEMMs, 8 rows (4 node-pairs) x 4 cols per thread ----
    int tx = tid & 15;          // cols 4tx..4tx+3
    int ty = tid >> 4;          // rows 8ty..8ty+7
    int base = blockIdx.x * TPB;
    int rbase = ty * 8;

    const float RS = rsqrtf(1.0f + 1e-5f);
    float4 gm  = ((const float4*)gam)[tx];
    float4 bt  = ((const float4*)bet)[tx];
    float4 bb1 = ((const float4*)b1)[tx];
    float4 bb2 = ((const float4*)b2)[tx];
    float gs[4], sh[4];
    gs[0] = gm.x * RS; gs[1] = gm.y * RS; gs[2] = gm.z * RS; gs[3] = gm.w * RS;
    sh[0] = bt.x + bb1.x * gs[0]; sh[1] = bt.y + bb1.y * gs[1];
    sh[2] = bt.z + bb1.z * gs[2]; sh[3] = bt.w + bb1.w * gs[3];

    ull acc[4][4];   // [node-pair][col], each = 2 packed fp32 rows
    #pragma unroll
    for (int p = 0; p < 4; p++)
        #pragma unroll
        for (int c = 0; c < 4; c++) acc[p][c] = 0ULL;

    const float4* w1v = (const float4*)sW1;

    #pragma unroll 4
    for (int k = 0; k < 64; k++) {
        float4 w = w1v[k * 16 + tx];
        ull wx = pk2(w.x, w.x), wy = pk2(w.y, w.y);
        ull wz = pk2(w.z, w.z), ww = pk2(w.w, w.w);
        const float* zr = &sZT[k * ZT + rbase];
        #pragma unroll
        for (int p = 0; p < 4; p++) {
            ull z = *(const ull*)(zr + 2 * p);
            ffma2(acc[p][0], z, wx);
            ffma2(acc[p][1], z, wy);
            ffma2(acc[p][2], z, wz);
            ffma2(acc[p][3], z, ww);
        }
    }
    __syncthreads();   // all zT reads done before overwriting with y

    // BN + ReLU, write y back k-major (col 4tx+c becomes k of GEMM2)
    #pragma unroll
    for (int p = 0; p < 4; p++) {
        #pragma unroll
        for (int c = 0; c < 4; c++) {
            float2 v = *(float2*)&acc[p][c];
            float2 y;
            y.x = fmaxf(v.x * gs[c] + sh[c], 0.f);
            y.y = fmaxf(v.y * gs[c] + sh[c], 0.f);
            *(float2*)&sZT[(4 * tx + c) * ZT + rbase + 2 * p] = y;
        }
    }
    __syncthreads();

    #pragma unroll
    for (int p = 0; p < 4; p++)
        #pragma unroll
        for (int c = 0; c < 4; c++) acc[p][c] = 0ULL;

    const float4* w2v = (const float4*)sW2;
    #pragma unroll 4
    for (int k = 0; k < 64; k++) {
        float4 w = w2v[k * 16 + tx];
        ull wx = pk2(w.x, w.x), wy = pk2(w.y, w.y);
        ull wz = pk2(w.z, w.z), ww = pk2(w.w, w.w);
        const float* zr = &sZT[k * ZT + rbase];
        #pragma unroll
        for (int p = 0; p < 4; p++) {
            ull z = *(const ull*)(zr + 2 * p);
            ffma2(acc[p][0], z, wx);
            ffma2(acc[p][1], z, wy);
            ffma2(acc[p][2], z, wz);
            ffma2(acc[p][3], z, ww);
        }
    }

    float4* out4 = (float4*)hout;
    #pragma unroll
    for (int p = 0; p < 4; p++) {
        float2 v0 = *(float2*)&acc[p][0];
        float2 v1 = *(float2*)&acc[p][1];
        float2 v2 = *(float2*)&acc[p][2];
        float2 v3 = *(float2*)&acc[p][3];
        int n0 = base + rbase + 2 * p;
        if (n0 < NN) {
            float4 o;
            o.x = fmaxf(v0.x + bb2.x, 0.f);
            o.y = fmaxf(v1.x + bb2.y, 0.f);
            o.z = fmaxf(v2.x + bb2.z, 0.f);
            o.w = fmaxf(v3.x + bb2.w, 0.f);
            out4[n0 * 16 + tx] = o;
        }
        if (n0 + 1 < NN) {
            float4 o;
            o.x = fmaxf(v0.y + bb2.x, 0.f);
            o.y = fmaxf(v1.y + bb2.y, 0.f);
            o.z = fmaxf(v2.y + bb2.z, 0.f);
            o.w = fmaxf(v3.y + bb2.w, 0.f);
            out4[(n0 + 1) * 16 + tx] = o;
        }
    }
}

// ---------------- pooling over sorted batch ----------------
__global__ void k_pool(const int* __restrict__ batch) {
    int tid = threadIdx.x;
    int go = tid >> 6;
    int d  = tid & 63;
    int start = blockIdx.x * 256 + go * 64;
    if (start >= NN) return;
    int end = min(start + 64, NN);
    const float* h = g_bufA;    // final features after layer 4
    int gcur = batch[start];
    float acc = 0.f;
    for (int n = start; n < end; n++) {
        int bg = batch[n];
        float v = h[n * 64 + d];
        if (bg != gcur) {
            atomicAdd(&g_pool[gcur * 64 + d], acc);
            acc = 0.f;
            gcur = bg;
        }
        acc += v;
    }
    atomicAdd(&g_pool[gcur * 64 + d], acc);
}

// ---------------- final linear + relu ----------------
__global__ void k_final(const float* __restrict__ W, const float* __restrict__ b,
                        float* __restrict__ out) {
    int idx = blockIdx.x * blockDim.x + threadIdx.x;
    int g = idx >> 6;
    int c = idx & 63;
    float acc = b[c];
    #pragma unroll 8
    for (int k = 0; k < 64; k++)
        acc += g_pool[g * 64 + k] * W[k * 64 + c];
    out[idx] = fmaxf(acc, 0.f);
}

// ---------------- launch ----------------
extern "C" void kernel_launch(void* const* d_in, const int* in_sizes, int n_in,
                              void* d_out, int out_size) {
    const float* x      = (const float*)d_in[0];
    const int*   ei     = (const int*)d_in[1];
    const int*   batch  = (const int*)d_in[2];
    const float* W1s    = (const float*)d_in[3];
    const float* b1s    = (const float*)d_in[4];
    const float* gammas = (const float*)d_in[5];
    const float* betas  = (const float*)d_in[6];
    const float* W2s    = (const float*)d_in[7];
    const float* b2s    = (const float*)d_in[8];
    const float* lin1_w = (const float*)d_in[9];
    const float* lin1_b = (const float*)d_in[10];
    float* out = (float*)d_out;

    const int SMEM_BYTES = (4096 + 4096 + 64 * ZT) * (int)sizeof(float);  // 66048
    cudaFuncSetAttribute(k_layer, cudaFuncAttributeMaxDynamicSharedMemorySize,
                         SMEM_BYTES);

    k_zero<<<256, 256>>>();
    k_hist<<<(NE + 255) / 256, 256>>>(ei);
    k_scan1<<<NSCAN, SCAN_B>>>();
    k_scan2<<<1, 256>>>();
    k_scan3<<<(NN + 256) / 256, 256>>>();
    k_fill<<<(NE + 255) / 256, 256>>>(ei);

    int nblocks = (NN + TPB - 1) / TPB;  // 782
    for (int l = 0; l < 5; l++) {
        k_layer<<<nblocks, 256, SMEM_BYTES>>>(
            x, W1s + l * 4096, b1s + l * 64, gammas + l * 64, betas + l * 64,
            W2s + l * 4096, b2s + l * 64, l);
    }

    k_pool<<<(NN + 255) / 256, 256>>>(batch);
    k_final<<<32, 256>>>(lin1_w, lin1_b, out);
}